// round 13
// baseline (speedup 1.0000x reference)
#include <cuda_runtime.h>
#include <cuda_fp16.h>

// PPISP pipeline. Round 13 = R11 (best) with the distance-2 pipeline loop
// unrolled 2x: buffer sets alternate roles via renaming instead of the
// 14-MOV/iter rotation. Same tables, packing, regs budget as R11.
//  - frame record 24B mixed: s_q {m00,m11,m22,h2(m01,m02)} + s_u 8B
//  - camera: s_Pa[j*4+c] = {h2(v0,v1), h2(p2,p3), h2(p4,mhd), a},
//    s_HC[c] = {h2(hc,hb) x3};  mhd = -d*0.5/c, hc = 0.5/c, hb = 0.5*b
//  - out = hb + hb*tanh(fma(xp, hc, mhd)),  xp = ex2(a*lg2(max(y,1e-6)))
//  launch_bounds(256,5): 51-reg cap, 40 warps/SM.

#define MAX_F 4096

__device__ float4 g_q[MAX_F];
__device__ uint2  g_u[MAX_F];
__device__ __align__(128) float4 g_Pa[3 * 4];   // [j][c]
__device__ __align__(64)  float4 g_HC[4];

__device__ __forceinline__ unsigned int f2h2(float a, float b) {
    __half2 h = __floats2half2_rn(a, b);
    return *reinterpret_cast<unsigned int*>(&h);
}
__device__ __forceinline__ float2 h22f2(unsigned int u) {
    __half2 h = *reinterpret_cast<__half2*>(&u);
    return __half22float2(h);
}

__global__ void ppisp_precompute(const float* __restrict__ expo,
                                 const float* __restrict__ vig,
                                 const float* __restrict__ colp,
                                 const float* __restrict__ crf,
                                 int F, int C)
{
    int t = blockIdx.x * blockDim.x + threadIdx.x;
    if (t < F) {
        float e  = exp2f(expo[t]);
        const float* cp = colp + t * 8;
        float s0 = e * expf(cp[0]);
        float s1 = e;
        float s2 = e * expf(cp[1]);
        float o0 = cp[2], o1 = cp[3], o2 = cp[4];
        float o3 = cp[5], o4 = cp[6], o5 = cp[7];
        float m00 = (1.0f - o0 - o1) * s0, m01 = o0 * s1, m02 = o1 * s2;
        float m10 = o2 * s0, m11 = (1.0f - o2 - o3) * s1, m12 = o3 * s2;
        float m20 = o4 * s0, m21 = o5 * s1, m22 = (1.0f - o4 - o5) * s2;
        float4 q;
        q.x = m00; q.y = m11; q.z = m22;
        q.w = __uint_as_float(f2h2(m01, m02));
        g_q[t] = q;
        g_u[t] = make_uint2(f2h2(m10, m12), f2h2(m20, m21));
    }
    if (blockIdx.x == 0 && (int)threadIdx.x < C * 3 && (int)threadIdx.x < 12) {
        int c = threadIdx.x / 3;
        int j = threadIdx.x % 3;
        const float* vp = vig + c * 15 + j * 5;
        const float* kp = crf + c * 12 + j * 4;
        float a  = log1pf(expf(kp[0])) + 0.3f;   // accurate softplus (once)
        float cc = log1pf(expf(kp[2])) + 0.1f;
        float d  = kp[3];
        float hc  = 0.5f / cc;
        float mhd = -d * hc;
        float4 P;
        P.x = __uint_as_float(f2h2(vp[0], vp[1]));
        P.y = __uint_as_float(f2h2(vp[2], vp[3]));
        P.z = __uint_as_float(f2h2(vp[4], mhd));
        P.w = a;
        g_Pa[j * 4 + c] = P;
    }
    if (blockIdx.x == 0 && (int)threadIdx.x < C && (int)threadIdx.x < 4) {
        int c = threadIdx.x;
        const float* kp = crf + c * 12;
        float4 H; float* Hf = (float*)&H;
#pragma unroll
        for (int j = 0; j < 3; j++) {
            float b  = log1pf(expf(kp[4 * j + 1])) + 0.3f;
            float cc = log1pf(expf(kp[4 * j + 2])) + 0.1f;
            Hf[j] = __uint_as_float(f2h2(0.5f / cc, 0.5f * b));
        }
        Hf[3] = 0.0f;
        g_HC[c] = H;
    }
}

__device__ __forceinline__ float fast_lg2(float x) {
    float y; asm("lg2.approx.f32 %0, %1;" : "=f"(y) : "f"(x)); return y;
}
__device__ __forceinline__ float fast_ex2(float x) {
    float y; asm("ex2.approx.f32 %0, %1;" : "=f"(y) : "f"(x)); return y;
}
__device__ __forceinline__ float fast_tanh(float x) {
    float y; asm("tanh.approx.f32 %0, %1;" : "=f"(y) : "f"(x)); return y;
}

struct PtIn {
    float r, g, b, px, py;
    int c, f;
};

__device__ __forceinline__ PtIn load_pt(const float* __restrict__ rgb,
                                        const float* __restrict__ coords,
                                        const int* __restrict__ cam,
                                        const int* __restrict__ frm,
                                        int i)
{
    PtIn p;
    p.r  = __ldcs(rgb + 3 * i + 0);
    p.g  = __ldcs(rgb + 3 * i + 1);
    p.b  = __ldcs(rgb + 3 * i + 2);
    p.px = __ldcs(coords + 2 * i + 0);
    p.py = __ldcs(coords + 2 * i + 1);
    p.c  = __ldcs(cam + i);
    p.f  = __ldcs(frm + i);
    return p;
}

__device__ __forceinline__ void compute_pt(
    const PtIn& a, int i,
    float invW2, float invH2,
    const float4* __restrict__ s_q, const uint2* __restrict__ s_u,
    const float4* __restrict__ s_Pa, const float4* __restrict__ s_HC,
    float* __restrict__ out)
{
    float u = fmaf(a.px, invW2, -1.0f);
    float v = fmaf(a.py, invH2, -1.0f);

    float rgbv[3] = {a.r, a.g, a.b};
    float t[3], aj[3], mhdj[3];
#pragma unroll
    for (int j = 0; j < 3; j++) {
        float4 P = s_Pa[j * 4 + a.c];
        float2 v01 = h22f2(__float_as_uint(P.x));
        float2 p23 = h22f2(__float_as_uint(P.y));
        float2 p4m = h22f2(__float_as_uint(P.z));
        float du = u - v01.x;
        float dv = v - v01.y;
        float r2 = fmaf(du, du, dv * dv);
        float gnv = fmaf(r2, fmaf(r2, fmaf(r2, p4m.x, p23.y), p23.x), 1.0f);
        t[j]    = rgbv[j] * gnv;
        aj[j]   = P.w;
        mhdj[j] = p4m.y;
    }

    float4 q  = s_q[a.f];
    uint2  uo = s_u[a.f];
    float2 m0102 = h22f2(__float_as_uint(q.w));
    float2 m1012 = h22f2(uo.x);
    float2 m2021 = h22f2(uo.y);

    float y0 = fmaf(q.x,     t[0], fmaf(m0102.x, t[1], m0102.y * t[2]));
    float y1 = fmaf(m1012.x, t[0], fmaf(q.y,     t[1], m1012.y * t[2]));
    float y2 = fmaf(m2021.x, t[0], fmaf(m2021.y, t[1], q.z     * t[2]));
    float yv[3] = {y0, y1, y2};

    float4 HC = s_HC[a.c];
    const float* Hf = (const float*)&HC;
#pragma unroll
    for (int j = 0; j < 3; j++) {
        float2 hcb = h22f2(__float_as_uint(Hf[j]));
        float xp  = fast_ex2(aj[j] * fast_lg2(fmaxf(yv[j], 1e-6f)));
        float arg = fmaf(xp, hcb.x, mhdj[j]);
        __stcs(out + 3 * i + j, fmaf(hcb.y, fast_tanh(arg), hcb.y));
    }
}

__global__ void __launch_bounds__(256, 5)
ppisp_main(const float* __restrict__ rgb,
           const float* __restrict__ coords,
           const int*   __restrict__ cam,
           const int*   __restrict__ frm,
           const int*   __restrict__ pW,
           const int*   __restrict__ pH,
           float* __restrict__ out,
           int B, int F)
{
    extern __shared__ float4 smbase[];
    float4* s_q  = smbase;                  // [F] 16B
    float4* s_Pa = s_q + F;                 // [12]
    float4* s_HC = s_Pa + 12;               // [4]
    uint2*  s_u  = (uint2*)(s_HC + 4);      // [F] 8B

    for (int i = threadIdx.x; i < F; i += blockDim.x) {
        s_q[i] = g_q[i];
        s_u[i] = g_u[i];
    }
    if (threadIdx.x < 12) s_Pa[threadIdx.x] = g_Pa[threadIdx.x];
    if (threadIdx.x < 4)  s_HC[threadIdx.x] = g_HC[threadIdx.x];
    __syncthreads();

    float invW2 = 2.0f / (float)__ldg(pW);
    float invH2 = 2.0f / (float)__ldg(pH);

    int stride = gridDim.x * blockDim.x;
    int i = blockIdx.x * blockDim.x + threadIdx.x;
    if (i >= B) return;

    // distance-2 pipeline, unrolled 2x (A/B/C alternate roles, no rotation MOVs)
    PtIn A = load_pt(rgb, coords, cam, frm, i);
    bool hasB = (i + stride < B);
    PtIn Bb;
    if (hasB) Bb = load_pt(rgb, coords, cam, frm, i + stride);
    PtIn Cc;

    while (true) {
        // iteration k: current = A, prefetch into C
        bool hasC = (i + 2 * stride < B);
        if (hasC) Cc = load_pt(rgb, coords, cam, frm, i + 2 * stride);
        compute_pt(A, i, invW2, invH2, s_q, s_u, s_Pa, s_HC, out);
        if (!hasB) break;
        i += stride;

        // iteration k+1: current = B, prefetch into A
        bool hasA = (i + 2 * stride < B);
        if (hasA) A = load_pt(rgb, coords, cam, frm, i + 2 * stride);
        compute_pt(Bb, i, invW2, invH2, s_q, s_u, s_Pa, s_HC, out);
        if (!hasC) break;
        i += stride;

        // iteration k+2: current = C, prefetch into B
        hasB = (i + 2 * stride < B);
        if (hasB) Bb = load_pt(rgb, coords, cam, frm, i + 2 * stride);
        compute_pt(Cc, i, invW2, invH2, s_q, s_u, s_Pa, s_HC, out);
        if (!hasA) break;
        i += stride;

        // rotate roles: A holds next current; B holds the one after; C free
        PtIn tmp = A; A = Cc; Cc = tmp;   // A<-? — realign: current=A(loaded k+1 slot)
        // After the three-iteration cycle the roles are again A=current,
        // B=next, C=free, because:
        //   k   consumed A, loaded C
        //   k+1 consumed B, loaded A
        //   k+2 consumed C, loaded B
        // so entering the next cycle: current should be the A loaded at k+1.
        // The swap above is a no-op for correctness concern: undo it.
        tmp = A; A = Cc; Cc = tmp;        // undo (kept for clarity; compiler elides)
    }
}

extern "C" void kernel_launch(void* const* d_in, const int* in_sizes, int n_in,
                              void* d_out, int out_size) {
    const float* expo   = (const float*)d_in[0];
    const float* vig    = (const float*)d_in[1];
    const float* colp   = (const float*)d_in[2];
    const float* crf    = (const float*)d_in[3];
    const float* rgb    = (const float*)d_in[4];
    const float* coords = (const float*)d_in[5];
    const int*   cam    = (const int*)d_in[6];
    const int*   frm    = (const int*)d_in[7];
    const int*   pW     = (const int*)d_in[8];
    const int*   pH     = (const int*)d_in[9];
    float* out = (float*)d_out;

    int F = in_sizes[0];
    int C = in_sizes[1] / 15;
    int B = in_sizes[6];
    if (F > MAX_F) F = MAX_F;   // table capacity guard (problem uses F=1000)

    // s_q[F] + s_Pa[12] + s_HC[4] + s_u[F]
    size_t shmem = (size_t)F * 16 + 16 * 16 + (size_t)F * 8;

    {
        int pthreads = 256;
        int pwork = (F > C * 3) ? F : C * 3;
        int pblocks = (pwork + pthreads - 1) / pthreads;
        ppisp_precompute<<<pblocks, pthreads>>>(expo, vig, colp, crf, F, C);
    }

    static bool attr_done = false;
    if (!attr_done) {
        cudaFuncSetAttribute(ppisp_main,
                             cudaFuncAttributeMaxDynamicSharedMemorySize,
                             (int)shmem > 49152 ? (int)shmem : 49152);
        attr_done = true;
    }

    int blocks = (B + 255) / 256;
    int maxb = 148 * 5;
    if (blocks > maxb) blocks = maxb;
    ppisp_main<<<blocks, 256, shmem>>>(rgb, coords, cam, frm, pW, pH,
                                       out, B, F);
}

// round 14
// speedup vs baseline: 1.1327x; 1.1327x over previous
#include <cuda_runtime.h>
#include <cuda_fp16.h>

// PPISP pipeline. Round 14 = R11 (best: distance-2 rotating pipeline) with
// the vignette for channels 0,1 computed directly in half2 (params stay
// packed -> kills ~18 F2F unpacks/pt), fp32 finish for precision.
//  - frame record 24B mixed: s_q {m00,m11,m22,h2(m01,m02)} + s_u 8B
//  - camera per c: VA={h2 v0,v1,p2,p3 pairs}, VB={h2 p4pair, v0_2,v1_2,p2_2},
//    VC={p3_2,p4_2,a_2,mhd_2}, CR={a_0,a_1,mhd_0,mhd_1}, HC={h2(hc,hb) x3}
//  - out = hb + hb*tanh(fma(xp, hc, mhd)),  xp = ex2(a*lg2(max(y,1e-6)))
//  launch_bounds(256,5): 51-reg cap, 40 warps/SM.

#define MAX_F 4096

__device__ float4 g_q[MAX_F];
__device__ uint2  g_u[MAX_F];
__device__ __align__(64) float4 g_VA[4];
__device__ __align__(64) float4 g_VB[4];
__device__ __align__(64) float4 g_VC[4];
__device__ __align__(64) float4 g_CR[4];
__device__ __align__(64) float4 g_HC[4];

__device__ __forceinline__ unsigned int f2h2(float a, float b) {
    __half2 h = __floats2half2_rn(a, b);
    return *reinterpret_cast<unsigned int*>(&h);
}
__device__ __forceinline__ float2 h22f2(unsigned int u) {
    __half2 h = *reinterpret_cast<__half2*>(&u);
    return __half22float2(h);
}
__device__ __forceinline__ __half2 u2h2(unsigned int u) {
    return *reinterpret_cast<__half2*>(&u);
}

__global__ void ppisp_precompute(const float* __restrict__ expo,
                                 const float* __restrict__ vig,
                                 const float* __restrict__ colp,
                                 const float* __restrict__ crf,
                                 int F, int C)
{
    int t = blockIdx.x * blockDim.x + threadIdx.x;
    if (t < F) {
        float e  = exp2f(expo[t]);
        const float* cp = colp + t * 8;
        float s0 = e * expf(cp[0]);
        float s1 = e;
        float s2 = e * expf(cp[1]);
        float o0 = cp[2], o1 = cp[3], o2 = cp[4];
        float o3 = cp[5], o4 = cp[6], o5 = cp[7];
        float m00 = (1.0f - o0 - o1) * s0, m01 = o0 * s1, m02 = o1 * s2;
        float m10 = o2 * s0, m11 = (1.0f - o2 - o3) * s1, m12 = o3 * s2;
        float m20 = o4 * s0, m21 = o5 * s1, m22 = (1.0f - o4 - o5) * s2;
        float4 q;
        q.x = m00; q.y = m11; q.z = m22;
        q.w = __uint_as_float(f2h2(m01, m02));
        g_q[t] = q;
        g_u[t] = make_uint2(f2h2(m10, m12), f2h2(m20, m21));
    }
    if (blockIdx.x == 0 && (int)threadIdx.x < C && (int)threadIdx.x < 4) {
        int c = threadIdx.x;
        const float* vp0 = vig + c * 15 + 0;
        const float* vp1 = vig + c * 15 + 5;
        const float* vp2 = vig + c * 15 + 10;
        const float* kp  = crf + c * 12;

        float a0 = log1pf(expf(kp[0]))  + 0.3f;
        float b0 = log1pf(expf(kp[1]))  + 0.3f;
        float c0 = log1pf(expf(kp[2]))  + 0.1f;
        float d0 = kp[3];
        float a1 = log1pf(expf(kp[4]))  + 0.3f;
        float b1 = log1pf(expf(kp[5]))  + 0.3f;
        float c1 = log1pf(expf(kp[6]))  + 0.1f;
        float d1 = kp[7];
        float a2 = log1pf(expf(kp[8]))  + 0.3f;
        float b2 = log1pf(expf(kp[9]))  + 0.3f;
        float c2 = log1pf(expf(kp[10])) + 0.1f;
        float d2 = kp[11];

        float hc0 = 0.5f / c0, hc1 = 0.5f / c1, hc2 = 0.5f / c2;

        float4 VA;
        VA.x = __uint_as_float(f2h2(vp0[0], vp1[0]));   // v0 pair
        VA.y = __uint_as_float(f2h2(vp0[1], vp1[1]));   // v1 pair
        VA.z = __uint_as_float(f2h2(vp0[2], vp1[2]));   // p2 pair
        VA.w = __uint_as_float(f2h2(vp0[3], vp1[3]));   // p3 pair
        g_VA[c] = VA;

        float4 VB;
        VB.x = __uint_as_float(f2h2(vp0[4], vp1[4]));   // p4 pair
        VB.y = vp2[0];                                   // v0_2
        VB.z = vp2[1];                                   // v1_2
        VB.w = vp2[2];                                   // p2_2
        g_VB[c] = VB;

        g_VC[c] = make_float4(vp2[3], vp2[4], a2, -d2 * hc2);
        g_CR[c] = make_float4(a0, a1, -d0 * hc0, -d1 * hc1);

        float4 H;
        H.x = __uint_as_float(f2h2(hc0, 0.5f * b0));
        H.y = __uint_as_float(f2h2(hc1, 0.5f * b1));
        H.z = __uint_as_float(f2h2(hc2, 0.5f * b2));
        H.w = 0.0f;
        g_HC[c] = H;
    }
}

__device__ __forceinline__ float fast_lg2(float x) {
    float y; asm("lg2.approx.f32 %0, %1;" : "=f"(y) : "f"(x)); return y;
}
__device__ __forceinline__ float fast_ex2(float x) {
    float y; asm("ex2.approx.f32 %0, %1;" : "=f"(y) : "f"(x)); return y;
}
__device__ __forceinline__ float fast_tanh(float x) {
    float y; asm("tanh.approx.f32 %0, %1;" : "=f"(y) : "f"(x)); return y;
}

struct PtIn {
    float r, g, b, px, py;
    int c, f;
};

__device__ __forceinline__ PtIn load_pt(const float* __restrict__ rgb,
                                        const float* __restrict__ coords,
                                        const int* __restrict__ cam,
                                        const int* __restrict__ frm,
                                        int i)
{
    PtIn p;
    p.r  = __ldcs(rgb + 3 * i + 0);
    p.g  = __ldcs(rgb + 3 * i + 1);
    p.b  = __ldcs(rgb + 3 * i + 2);
    p.px = __ldcs(coords + 2 * i + 0);
    p.py = __ldcs(coords + 2 * i + 1);
    p.c  = __ldcs(cam + i);
    p.f  = __ldcs(frm + i);
    return p;
}

__global__ void __launch_bounds__(256, 5)
ppisp_main(const float* __restrict__ rgb,
           const float* __restrict__ coords,
           const int*   __restrict__ cam,
           const int*   __restrict__ frm,
           const int*   __restrict__ pW,
           const int*   __restrict__ pH,
           float* __restrict__ out,
           int B, int F)
{
    extern __shared__ float4 smbase[];
    float4* s_q  = smbase;                  // [F] 16B
    float4* s_VA = s_q + F;                 // [4]
    float4* s_VB = s_VA + 4;                // [4]
    float4* s_VC = s_VB + 4;                // [4]
    float4* s_CR = s_VC + 4;                // [4]
    float4* s_HC = s_CR + 4;                // [4]
    uint2*  s_u  = (uint2*)(s_HC + 4);      // [F] 8B

    for (int i = threadIdx.x; i < F; i += blockDim.x) {
        s_q[i] = g_q[i];
        s_u[i] = g_u[i];
    }
    if (threadIdx.x < 4) {
        s_VA[threadIdx.x] = g_VA[threadIdx.x];
        s_VB[threadIdx.x] = g_VB[threadIdx.x];
        s_VC[threadIdx.x] = g_VC[threadIdx.x];
        s_CR[threadIdx.x] = g_CR[threadIdx.x];
        s_HC[threadIdx.x] = g_HC[threadIdx.x];
    }
    __syncthreads();

    float invW2 = 2.0f / (float)__ldg(pW);
    float invH2 = 2.0f / (float)__ldg(pH);

    int stride = gridDim.x * blockDim.x;
    int i = blockIdx.x * blockDim.x + threadIdx.x;
    if (i >= B) return;

    // distance-2 pipeline: a = current, b = arrived, cbuf = in-flight
    PtIn a = load_pt(rgb, coords, cam, frm, i);
    bool hasb = (i + stride < B);
    PtIn b;
    if (hasb) b = load_pt(rgb, coords, cam, frm, i + stride);

    while (true) {
        bool hasc = (i + 2 * stride < B);
        PtIn cbuf;
        if (hasc) cbuf = load_pt(rgb, coords, cam, frm, i + 2 * stride);

        // ---- compute current point (a) ----
        {
            int c = a.c;
            float u = fmaf(a.px, invW2, -1.0f);
            float v = fmaf(a.py, invH2, -1.0f);

            // channels 0,1: half2 vignette (params stay packed, no unpacks)
            float4 VA = s_VA[c];
            float4 VB = s_VB[c];
            __half2 U2 = __float2half2_rn(u);
            __half2 V2 = __float2half2_rn(v);
            __half2 du2 = __hsub2(U2, u2h2(__float_as_uint(VA.x)));
            __half2 dv2 = __hsub2(V2, u2h2(__float_as_uint(VA.y)));
            __half2 r22 = __hfma2(du2, du2, __hmul2(dv2, dv2));
            __half2 pl2 = __hfma2(r22,
                                  __hfma2(r22, u2h2(__float_as_uint(VB.x)),
                                          u2h2(__float_as_uint(VA.w))),
                                  u2h2(__float_as_uint(VA.z)));
            float2 r2f = __half22float2(r22);
            float2 plf = __half22float2(pl2);
            float t0 = a.r * fmaf(r2f.x, plf.x, 1.0f);
            float t1 = a.g * fmaf(r2f.y, plf.y, 1.0f);

            // channel 2: fp32 vignette
            float4 VC = s_VC[c];
            float du = u - VB.y;
            float dv = v - VB.z;
            float r2s = fmaf(du, du, dv * dv);
            float gn2 = fmaf(r2s, fmaf(r2s, fmaf(r2s, VC.y, VC.x), VB.w), 1.0f);
            float t2 = a.b * gn2;

            // frame matrix
            float4 q  = s_q[a.f];
            uint2  uo = s_u[a.f];
            float2 m0102 = h22f2(__float_as_uint(q.w));
            float2 m1012 = h22f2(uo.x);
            float2 m2021 = h22f2(uo.y);

            float y0 = fmaf(q.x,     t0, fmaf(m0102.x, t1, m0102.y * t2));
            float y1 = fmaf(m1012.x, t0, fmaf(q.y,     t1, m1012.y * t2));
            float y2 = fmaf(m2021.x, t0, fmaf(m2021.y, t1, q.z     * t2));
            float yv[3] = {y0, y1, y2};

            // CRF
            float4 CR = s_CR[c];
            float aj[3]   = {CR.x, CR.y, VC.z};
            float mhdj[3] = {CR.z, CR.w, VC.w};
            float4 HC = s_HC[c];
            const float* Hf = (const float*)&HC;
#pragma unroll
            for (int j = 0; j < 3; j++) {
                float2 hcb = h22f2(__float_as_uint(Hf[j]));
                float xp  = fast_ex2(aj[j] * fast_lg2(fmaxf(yv[j], 1e-6f)));
                float arg = fmaf(xp, hcb.x, mhdj[j]);
                __stcs(out + 3 * i + j, fmaf(hcb.y, fast_tanh(arg), hcb.y));
            }
        }

        if (!hasb) break;
        a = b;
        b = cbuf;
        hasb = hasc;
        i += stride;
    }
}

extern "C" void kernel_launch(void* const* d_in, const int* in_sizes, int n_in,
                              void* d_out, int out_size) {
    const float* expo   = (const float*)d_in[0];
    const float* vig    = (const float*)d_in[1];
    const float* colp   = (const float*)d_in[2];
    const float* crf    = (const float*)d_in[3];
    const float* rgb    = (const float*)d_in[4];
    const float* coords = (const float*)d_in[5];
    const int*   cam    = (const int*)d_in[6];
    const int*   frm    = (const int*)d_in[7];
    const int*   pW     = (const int*)d_in[8];
    const int*   pH     = (const int*)d_in[9];
    float* out = (float*)d_out;

    int F = in_sizes[0];
    int C = in_sizes[1] / 15;
    int B = in_sizes[6];
    if (F > MAX_F) F = MAX_F;   // table capacity guard (problem uses F=1000)

    // s_q[F] + 5 camera tables (4 x float4 each) + s_u[F]
    size_t shmem = (size_t)F * 16 + 20 * 16 + (size_t)F * 8;

    {
        int pthreads = 256;
        int pwork = (F > C * 3) ? F : C * 3;
        int pblocks = (pwork + pthreads - 1) / pthreads;
        ppisp_precompute<<<pblocks, pthreads>>>(expo, vig, colp, crf, F, C);
    }

    static bool attr_done = false;
    if (!attr_done) {
        cudaFuncSetAttribute(ppisp_main,
                             cudaFuncAttributeMaxDynamicSharedMemorySize,
                             (int)shmem > 49152 ? (int)shmem : 49152);
        attr_done = true;
    }

    int blocks = (B + 255) / 256;
    int maxb = 148 * 5;
    if (blocks > maxb) blocks = maxb;
    ppisp_main<<<blocks, 256, shmem>>>(rgb, coords, cam, frm, pW, pH,
                                       out, B, F);
}

// round 16
// speedup vs baseline: 1.1981x; 1.0577x over previous
#include <cuda_runtime.h>
#include <cuda_fp16.h>

// PPISP pipeline. Round 16 = Round 15 resubmitted (R15 hit a broker/container
// infra failure; kernel never executed). R11 (best) with the precompute kernel
// FUSED into the main kernel: each block builds its smem tables directly from
// the raw inputs (replacing the global-table staging loads), removing the
// second graph node (~1us of bench time). Main loop is byte-for-byte R11.
//  - frame record 24B mixed: s_q {m00,m11,m22,h2(m01,m02)} + s_u 8B
//  - camera: s_Pa[j*4+c] = {h2(v0,v1), h2(p2,p3), h2(p4,mhd), a},
//    s_HC[c] = {h2(hc,hb) x3};  mhd = -d*0.5/c, hc = 0.5/c, hb = 0.5*b
//  - out = hb + hb*tanh(fma(xp, hc, mhd)),  xp = ex2(a*lg2(max(y,1e-6)))
//  launch_bounds(256,5): 51-reg cap, 40 warps/SM.

#define MAX_F 4096
#define LOG2E 1.44269504088896f
#define LN2   0.69314718055995f

__device__ __forceinline__ unsigned int f2h2(float a, float b) {
    __half2 h = __floats2half2_rn(a, b);
    return *reinterpret_cast<unsigned int*>(&h);
}
__device__ __forceinline__ float2 h22f2(unsigned int u) {
    __half2 h = *reinterpret_cast<__half2*>(&u);
    return __half22float2(h);
}

__device__ __forceinline__ float fast_lg2(float x) {
    float y; asm("lg2.approx.f32 %0, %1;" : "=f"(y) : "f"(x)); return y;
}
__device__ __forceinline__ float fast_ex2(float x) {
    float y; asm("ex2.approx.f32 %0, %1;" : "=f"(y) : "f"(x)); return y;
}
__device__ __forceinline__ float fast_tanh(float x) {
    float y; asm("tanh.approx.f32 %0, %1;" : "=f"(y) : "f"(x)); return y;
}
// softplus via MUFU: ln(1+e^x) = ln2 * lg2(1 + 2^(x*log2e)); err ~1e-7 here
__device__ __forceinline__ float softplus_fast(float x) {
    return LN2 * fast_lg2(1.0f + fast_ex2(x * LOG2E));
}

struct PtIn {
    float r, g, b, px, py;
    int c, f;
};

__device__ __forceinline__ PtIn load_pt(const float* __restrict__ rgb,
                                        const float* __restrict__ coords,
                                        const int* __restrict__ cam,
                                        const int* __restrict__ frm,
                                        int i)
{
    PtIn p;
    p.r  = __ldcs(rgb + 3 * i + 0);
    p.g  = __ldcs(rgb + 3 * i + 1);
    p.b  = __ldcs(rgb + 3 * i + 2);
    p.px = __ldcs(coords + 2 * i + 0);
    p.py = __ldcs(coords + 2 * i + 1);
    p.c  = __ldcs(cam + i);
    p.f  = __ldcs(frm + i);
    return p;
}

__global__ void __launch_bounds__(256, 5)
ppisp_main(const float* __restrict__ expo,
           const float* __restrict__ vig,
           const float* __restrict__ colp,
           const float* __restrict__ crf,
           const float* __restrict__ rgb,
           const float* __restrict__ coords,
           const int*   __restrict__ cam,
           const int*   __restrict__ frm,
           const int*   __restrict__ pW,
           const int*   __restrict__ pH,
           float* __restrict__ out,
           int B, int F)
{
    extern __shared__ float4 smbase[];
    float4* s_q  = smbase;                  // [F] 16B
    float4* s_Pa = s_q + F;                 // [12]
    float4* s_HC = s_Pa + 12;               // [4]
    uint2*  s_u  = (uint2*)(s_HC + 4);      // [F] 8B

    // ---- build frame table in-block (replaces precompute kernel + staging) ----
    for (int f = threadIdx.x; f < F; f += blockDim.x) {
        float e = fast_ex2(__ldg(expo + f));
        const float4* cp4 = (const float4*)(colp + f * 8);
        float4 c0 = __ldg(cp4 + 0);     // {wb0, wb1, o0, o1}
        float4 c1 = __ldg(cp4 + 1);     // {o2, o3, o4, o5}
        float s0 = e * fast_ex2(c0.x * LOG2E);
        float s1 = e;
        float s2 = e * fast_ex2(c0.y * LOG2E);
        float o0 = c0.z, o1 = c0.w, o2 = c1.x;
        float o3 = c1.y, o4 = c1.z, o5 = c1.w;
        float m00 = (1.0f - o0 - o1) * s0, m01 = o0 * s1, m02 = o1 * s2;
        float m10 = o2 * s0, m11 = (1.0f - o2 - o3) * s1, m12 = o3 * s2;
        float m20 = o4 * s0, m21 = o5 * s1, m22 = (1.0f - o4 - o5) * s2;
        float4 q;
        q.x = m00; q.y = m11; q.z = m22;
        q.w = __uint_as_float(f2h2(m01, m02));
        s_q[f] = q;
        s_u[f] = make_uint2(f2h2(m10, m12), f2h2(m20, m21));
    }

    // ---- build camera tables in-block ----
    if (threadIdx.x < 12) {
        int c = threadIdx.x / 3;
        int j = threadIdx.x % 3;
        const float* vp = vig + c * 15 + j * 5;
        const float* kp = crf + c * 12 + j * 4;
        float a  = softplus_fast(__ldg(kp + 0)) + 0.3f;
        float cc = softplus_fast(__ldg(kp + 2)) + 0.1f;
        float d  = __ldg(kp + 3);
        float hc  = 0.5f / cc;
        float mhd = -d * hc;
        float4 P;
        P.x = __uint_as_float(f2h2(__ldg(vp + 0), __ldg(vp + 1)));
        P.y = __uint_as_float(f2h2(__ldg(vp + 2), __ldg(vp + 3)));
        P.z = __uint_as_float(f2h2(__ldg(vp + 4), mhd));
        P.w = a;
        s_Pa[j * 4 + c] = P;
    }
    if (threadIdx.x < 4) {
        int c = threadIdx.x;
        const float* kp = crf + c * 12;
        float4 H; float* Hf = (float*)&H;
#pragma unroll
        for (int j = 0; j < 3; j++) {
            float b  = softplus_fast(__ldg(kp + 4 * j + 1)) + 0.3f;
            float cc = softplus_fast(__ldg(kp + 4 * j + 2)) + 0.1f;
            Hf[j] = __uint_as_float(f2h2(0.5f / cc, 0.5f * b));
        }
        Hf[3] = 0.0f;
        s_HC[c] = H;
    }
    __syncthreads();

    float invW2 = 2.0f / (float)__ldg(pW);
    float invH2 = 2.0f / (float)__ldg(pH);

    int stride = gridDim.x * blockDim.x;
    int i = blockIdx.x * blockDim.x + threadIdx.x;
    if (i >= B) return;

    // ---- R11 main loop: distance-2 rotating pipeline ----
    PtIn a = load_pt(rgb, coords, cam, frm, i);
    bool hasb = (i + stride < B);
    PtIn b;
    if (hasb) b = load_pt(rgb, coords, cam, frm, i + stride);

    while (true) {
        bool hasc = (i + 2 * stride < B);
        PtIn cbuf;
        if (hasc) cbuf = load_pt(rgb, coords, cam, frm, i + 2 * stride);

        // ---- compute current point (a) ----
        {
            float u = fmaf(a.px, invW2, -1.0f);
            float v = fmaf(a.py, invH2, -1.0f);

            float rgbv[3] = {a.r, a.g, a.b};
            float t[3], aj[3], mhdj[3];
#pragma unroll
            for (int j = 0; j < 3; j++) {
                float4 P = s_Pa[j * 4 + a.c];
                float2 v01 = h22f2(__float_as_uint(P.x));
                float2 p23 = h22f2(__float_as_uint(P.y));
                float2 p4m = h22f2(__float_as_uint(P.z));
                float du = u - v01.x;
                float dv = v - v01.y;
                float r2 = fmaf(du, du, dv * dv);
                float gnv = fmaf(r2, fmaf(r2, fmaf(r2, p4m.x, p23.y), p23.x), 1.0f);
                t[j]    = rgbv[j] * gnv;
                aj[j]   = P.w;
                mhdj[j] = p4m.y;
            }

            float4 q  = s_q[a.f];
            uint2  uo = s_u[a.f];
            float2 m0102 = h22f2(__float_as_uint(q.w));
            float2 m1012 = h22f2(uo.x);
            float2 m2021 = h22f2(uo.y);

            float y0 = fmaf(q.x,     t[0], fmaf(m0102.x, t[1], m0102.y * t[2]));
            float y1 = fmaf(m1012.x, t[0], fmaf(q.y,     t[1], m1012.y * t[2]));
            float y2 = fmaf(m2021.x, t[0], fmaf(m2021.y, t[1], q.z     * t[2]));
            float yv[3] = {y0, y1, y2};

            float4 HC = s_HC[a.c];
            const float* Hf = (const float*)&HC;
#pragma unroll
            for (int j = 0; j < 3; j++) {
                float2 hcb = h22f2(__float_as_uint(Hf[j]));
                float xp  = fast_ex2(aj[j] * fast_lg2(fmaxf(yv[j], 1e-6f)));
                float arg = fmaf(xp, hcb.x, mhdj[j]);
                __stcs(out + 3 * i + j, fmaf(hcb.y, fast_tanh(arg), hcb.y));
            }
        }

        if (!hasb) break;
        a = b;
        b = cbuf;
        hasb = hasc;
        i += stride;
    }
}

extern "C" void kernel_launch(void* const* d_in, const int* in_sizes, int n_in,
                              void* d_out, int out_size) {
    const float* expo   = (const float*)d_in[0];
    const float* vig    = (const float*)d_in[1];
    const float* colp   = (const float*)d_in[2];
    const float* crf    = (const float*)d_in[3];
    const float* rgb    = (const float*)d_in[4];
    const float* coords = (const float*)d_in[5];
    const int*   cam    = (const int*)d_in[6];
    const int*   frm    = (const int*)d_in[7];
    const int*   pW     = (const int*)d_in[8];
    const int*   pH     = (const int*)d_in[9];
    float* out = (float*)d_out;

    int F = in_sizes[0];
    int B = in_sizes[6];
    if (F > MAX_F) F = MAX_F;   // table capacity guard (problem uses F=1000)

    // s_q[F] + s_Pa[12] + s_HC[4] + s_u[F]
    size_t shmem = (size_t)F * 16 + 16 * 16 + (size_t)F * 8;

    static bool attr_done = false;
    if (!attr_done) {
        cudaFuncSetAttribute(ppisp_main,
                             cudaFuncAttributeMaxDynamicSharedMemorySize,
                             (int)shmem > 49152 ? (int)shmem : 49152);
        attr_done = true;
    }

    int blocks = (B + 255) / 256;
    int maxb = 148 * 5;
    if (blocks > maxb) blocks = maxb;
    ppisp_main<<<blocks, 256, shmem>>>(expo, vig, colp, crf, rgb, coords,
                                       cam, frm, pW, pH, out, B, F);
}